// round 11
// baseline (speedup 1.0000x reference)
#include <cuda_runtime.h>

// x: (B=64, C=128, T=10000) float32, row-major.
#define B_DIM 64
#define C_DIM 128
#define T_DIM 10000
#define T4    2500              // float4 per (b,c) row
#define K2_THREADS 512
#define K2_ITERS   5            // ceil(2500/512)

// K1 geometry: 8-way channel split.
#define K1_THREADS 256
#define K1_QPC  32              // quads per CTA
#define K1_GPC  8               // channel groups per CTA
#define K1_CPG  16              // channels per group (8*16 = 128)
#define K1_GRID ((B_DIM * T4) / K1_QPC)   // 160000/32 = 5000

// Per-(batch,time) channel means: 64*10000 floats = 2.56 MB (lives in L2 for K2).
__device__ float g_mu[B_DIM * T_DIM];

// ---------------------------------------------------------------------------
// K1: mu[b,t] = mean over channels, 8-way channel split.
// x loaded with DEFAULT policy (evict-normal): the last ~120MB K1 reads
// (high batches) stays resident in L2 so the REVERSED K2 can hit on it.
// Lanes 0-31 = consecutive quads -> 512B coalesced warp reads per channel.
// ---------------------------------------------------------------------------
__global__ __launch_bounds__(K1_THREADS)
void mu_kernel(const float* __restrict__ x) {
    __shared__ float4 part[K1_GPC][K1_QPC];     // 4 KB

    const int ql = threadIdx.x & (K1_QPC - 1);
    const int g  = threadIdx.x >> 5;            // channel group 0..7
    const int q  = blockIdx.x * K1_QPC + ql;    // global quad id (ascending b)
    const int b  = q / T4;
    const int i4 = q - b * T4;

    const float4* __restrict__ xp =
        reinterpret_cast<const float4*>(x)
        + ((size_t)b * C_DIM + (size_t)g * K1_CPG) * T4 + i4;

    float sx = 0.f, sy = 0.f, sz = 0.f, sw = 0.f;
#pragma unroll
    for (int c = 0; c < K1_CPG; ++c) {
        float4 v = xp[(size_t)c * T4];          // default policy: keep in L2
        sx += v.x; sy += v.y; sz += v.z; sw += v.w;
    }
    float4 p; p.x = sx; p.y = sy; p.z = sz; p.w = sw;
    part[g][ql] = p;
    __syncthreads();

    if (threadIdx.x < K1_QPC) {
        float4 a = part[0][ql];
#pragma unroll
        for (int gg = 1; gg < K1_GPC; ++gg) {
            float4 t = part[gg][ql];
            a.x += t.x; a.y += t.y; a.z += t.z; a.w += t.w;
        }
        const float inv = 1.0f / (float)C_DIM;
        a.x *= inv; a.y *= inv; a.z *= inv; a.w *= inv;
        reinterpret_cast<float4*>(g_mu)[(size_t)b * T4 + i4] = a;
    }
}

// ---------------------------------------------------------------------------
// K2: one CTA per (b,c) row, processed in REVERSE row order so the first
// waves read the x data K1 touched last (still L2-resident across the launch
// boundary — L2 persists, only L1 flushes). d = x - mu held in registers
// across the block reduction. x via __ldcs, out via __stcs (evict-first:
// K2's own streams self-evict instead of evicting the reusable x residue).
// ---------------------------------------------------------------------------
__global__ __launch_bounds__(K2_THREADS, 2)
void norm_kernel(const float* __restrict__ x, float* __restrict__ out) {
    __shared__ float red_s[16], red_s2[16];
    __shared__ float s_mean, s_inv;

    const int row = (B_DIM * C_DIM - 1) - blockIdx.x;   // reversed
    const int b   = row >> 7;

    const float4* __restrict__ xp =
        reinterpret_cast<const float4*>(x) + (size_t)row * T4;
    const float4* __restrict__ mp =
        reinterpret_cast<const float4*>(g_mu) + (size_t)b * T4;

    float4 xv[K2_ITERS], mv[K2_ITERS];
#pragma unroll
    for (int k = 0; k < K2_ITERS; ++k) {
        const int i = threadIdx.x + k * K2_THREADS;
        if (i < T4) {
            xv[k] = __ldcs(xp + i);
            mv[k] = mp[i];
        }
    }

    float s = 0.f, s2 = 0.f;
#pragma unroll
    for (int k = 0; k < K2_ITERS; ++k) {
        const int i = threadIdx.x + k * K2_THREADS;
        if (i < T4) {
            xv[k].x -= mv[k].x; xv[k].y -= mv[k].y;
            xv[k].z -= mv[k].z; xv[k].w -= mv[k].w;
            s  += xv[k].x + xv[k].y + xv[k].z + xv[k].w;
            s2 += xv[k].x * xv[k].x + xv[k].y * xv[k].y
                + xv[k].z * xv[k].z + xv[k].w * xv[k].w;
        }
    }

#pragma unroll
    for (int o = 16; o > 0; o >>= 1) {
        s  += __shfl_down_sync(0xffffffffu, s,  o);
        s2 += __shfl_down_sync(0xffffffffu, s2, o);
    }
    const int wid = threadIdx.x >> 5;
    const int lid = threadIdx.x & 31;
    if (lid == 0) { red_s[wid] = s; red_s2[wid] = s2; }
    __syncthreads();

    if (threadIdx.x < 32) {
        float a  = (lid < 16) ? red_s[lid]  : 0.f;
        float a2 = (lid < 16) ? red_s2[lid] : 0.f;
#pragma unroll
        for (int o = 8; o > 0; o >>= 1) {
            a  += __shfl_down_sync(0xffffffffu, a,  o);
            a2 += __shfl_down_sync(0xffffffffu, a2, o);
        }
        if (lid == 0) {
            const float invT = 1.0f / (float)T_DIM;
            float mean = a * invT;
            float var  = a2 * invT - mean * mean;
            float sd   = sqrtf(fmaxf(var, 0.0f));
            if (sd == 0.0f) sd = 1.0f;
            s_mean = mean;
            s_inv  = 1.0f / sd;
        }
    }
    __syncthreads();

    const float mean = s_mean;
    const float invs = s_inv;
    float4* __restrict__ op = reinterpret_cast<float4*>(out) + (size_t)row * T4;
#pragma unroll
    for (int k = 0; k < K2_ITERS; ++k) {
        const int i = threadIdx.x + k * K2_THREADS;
        if (i < T4) {
            float4 r;
            r.x = (xv[k].x - mean) * invs;
            r.y = (xv[k].y - mean) * invs;
            r.z = (xv[k].z - mean) * invs;
            r.w = (xv[k].w - mean) * invs;
            __stcs(op + i, r);
        }
    }
}

extern "C" void kernel_launch(void* const* d_in, const int* in_sizes, int n_in,
                              void* d_out, int out_size) {
    (void)in_sizes; (void)n_in; (void)out_size;
    const float* x   = (const float*)d_in[0];
    float*       out = (float*)d_out;

    mu_kernel<<<K1_GRID, K1_THREADS>>>(x);
    norm_kernel<<<B_DIM * C_DIM, K2_THREADS>>>(x, out);
}

// round 12
// speedup vs baseline: 1.0628x; 1.0628x over previous
#include <cuda_runtime.h>

// x: (B=64, C=128, T=10000) float32, row-major.
#define B_DIM 64
#define C_DIM 128
#define T_DIM 10000
#define T4    2500              // float4 per (b,c) row
#define K2_THREADS 512
#define K2_ITERS   5            // ceil(2500/512)

// K1 geometry: 8-way channel split.
#define K1_THREADS 256
#define K1_QPC  32              // quads per CTA
#define K1_GPC  8               // channel groups per CTA
#define K1_CPG  16              // channels per group (8*16 = 128)
#define K1_GRID ((B_DIM * T4) / K1_QPC)   // 160000/32 = 5000

// Batches >= this are loaded evict-normal in K1 so they stay L2-resident for
// the reversed K2 (16 batches * 5.12MB = 82MB, fits the 126MB L2 with room).
#define K1_KEEP_B 48

// Per-(batch,time) channel means: 64*10000 floats = 2.56 MB (lives in L2 for K2).
__device__ float g_mu[B_DIM * T_DIM];

// ---------------------------------------------------------------------------
// K1: mu[b,t] = mean over channels, 8-way channel split.
// Hybrid cache policy: __ldcs (evict-first) for the bulk (b < 48) so K1 keeps
// full streaming speed; default (evict-normal) for the last 16 batches so
// that data survives in L2 for the reversed K2 to hit.
// Lanes 0-31 = consecutive quads -> 512B coalesced warp reads per channel.
// ---------------------------------------------------------------------------
__global__ __launch_bounds__(K1_THREADS)
void mu_kernel(const float* __restrict__ x) {
    __shared__ float4 part[K1_GPC][K1_QPC];     // 4 KB

    const int ql = threadIdx.x & (K1_QPC - 1);
    const int g  = threadIdx.x >> 5;            // channel group 0..7
    const int q  = blockIdx.x * K1_QPC + ql;    // global quad id (ascending b)
    const int b  = q / T4;
    const int i4 = q - b * T4;

    const float4* __restrict__ xp =
        reinterpret_cast<const float4*>(x)
        + ((size_t)b * C_DIM + (size_t)g * K1_CPG) * T4 + i4;

    float sx = 0.f, sy = 0.f, sz = 0.f, sw = 0.f;
    if (b < K1_KEEP_B) {
#pragma unroll
        for (int c = 0; c < K1_CPG; ++c) {
            float4 v = __ldcs(xp + (size_t)c * T4);   // streamed, evict-first
            sx += v.x; sy += v.y; sz += v.z; sw += v.w;
        }
    } else {
#pragma unroll
        for (int c = 0; c < K1_CPG; ++c) {
            float4 v = xp[(size_t)c * T4];            // keep resident for K2
            sx += v.x; sy += v.y; sz += v.z; sw += v.w;
        }
    }
    float4 p; p.x = sx; p.y = sy; p.z = sz; p.w = sw;
    part[g][ql] = p;
    __syncthreads();

    if (threadIdx.x < K1_QPC) {
        float4 a = part[0][ql];
#pragma unroll
        for (int gg = 1; gg < K1_GPC; ++gg) {
            float4 t = part[gg][ql];
            a.x += t.x; a.y += t.y; a.z += t.z; a.w += t.w;
        }
        const float inv = 1.0f / (float)C_DIM;
        a.x *= inv; a.y *= inv; a.z *= inv; a.w *= inv;
        reinterpret_cast<float4*>(g_mu)[(size_t)b * T4 + i4] = a;
    }
}

// ---------------------------------------------------------------------------
// K2: one CTA per (b,c) row, processed in REVERSE row order so the first
// waves read the x batches K1 deliberately left in L2 (L2 persists across
// launches; only L1 flushes). d = x - mu held in registers across the block
// reduction. x via __ldcs (policy irrelevant on hits), out via __stcs
// (evict-first: K2's write stream self-evicts instead of the x residue).
// ---------------------------------------------------------------------------
__global__ __launch_bounds__(K2_THREADS, 2)
void norm_kernel(const float* __restrict__ x, float* __restrict__ out) {
    __shared__ float red_s[16], red_s2[16];
    __shared__ float s_mean, s_inv;

    const int row = (B_DIM * C_DIM - 1) - blockIdx.x;   // reversed
    const int b   = row >> 7;

    const float4* __restrict__ xp =
        reinterpret_cast<const float4*>(x) + (size_t)row * T4;
    const float4* __restrict__ mp =
        reinterpret_cast<const float4*>(g_mu) + (size_t)b * T4;

    float4 xv[K2_ITERS], mv[K2_ITERS];
#pragma unroll
    for (int k = 0; k < K2_ITERS; ++k) {
        const int i = threadIdx.x + k * K2_THREADS;
        if (i < T4) {
            xv[k] = __ldcs(xp + i);
            mv[k] = mp[i];
        }
    }

    float s = 0.f, s2 = 0.f;
#pragma unroll
    for (int k = 0; k < K2_ITERS; ++k) {
        const int i = threadIdx.x + k * K2_THREADS;
        if (i < T4) {
            xv[k].x -= mv[k].x; xv[k].y -= mv[k].y;
            xv[k].z -= mv[k].z; xv[k].w -= mv[k].w;
            s  += xv[k].x + xv[k].y + xv[k].z + xv[k].w;
            s2 += xv[k].x * xv[k].x + xv[k].y * xv[k].y
                + xv[k].z * xv[k].z + xv[k].w * xv[k].w;
        }
    }

#pragma unroll
    for (int o = 16; o > 0; o >>= 1) {
        s  += __shfl_down_sync(0xffffffffu, s,  o);
        s2 += __shfl_down_sync(0xffffffffu, s2, o);
    }
    const int wid = threadIdx.x >> 5;
    const int lid = threadIdx.x & 31;
    if (lid == 0) { red_s[wid] = s; red_s2[wid] = s2; }
    __syncthreads();

    if (threadIdx.x < 32) {
        float a  = (lid < 16) ? red_s[lid]  : 0.f;
        float a2 = (lid < 16) ? red_s2[lid] : 0.f;
#pragma unroll
        for (int o = 8; o > 0; o >>= 1) {
            a  += __shfl_down_sync(0xffffffffu, a,  o);
            a2 += __shfl_down_sync(0xffffffffu, a2, o);
        }
        if (lid == 0) {
            const float invT = 1.0f / (float)T_DIM;
            float mean = a * invT;
            float var  = a2 * invT - mean * mean;
            float sd   = sqrtf(fmaxf(var, 0.0f));
            if (sd == 0.0f) sd = 1.0f;
            s_mean = mean;
            s_inv  = 1.0f / sd;
        }
    }
    __syncthreads();

    const float mean = s_mean;
    const float invs = s_inv;
    float4* __restrict__ op = reinterpret_cast<float4*>(out) + (size_t)row * T4;
#pragma unroll
    for (int k = 0; k < K2_ITERS; ++k) {
        const int i = threadIdx.x + k * K2_THREADS;
        if (i < T4) {
            float4 r;
            r.x = (xv[k].x - mean) * invs;
            r.y = (xv[k].y - mean) * invs;
            r.z = (xv[k].z - mean) * invs;
            r.w = (xv[k].w - mean) * invs;
            __stcs(op + i, r);
        }
    }
}

extern "C" void kernel_launch(void* const* d_in, const int* in_sizes, int n_in,
                              void* d_out, int out_size) {
    (void)in_sizes; (void)n_in; (void)out_size;
    const float* x   = (const float*)d_in[0];
    float*       out = (float*)d_out;

    mu_kernel<<<K1_GRID, K1_THREADS>>>(x);
    norm_kernel<<<B_DIM * C_DIM, K2_THREADS>>>(x, out);
}